// round 1
// baseline (speedup 1.0000x reference)
#include <cuda_runtime.h>
#include <math.h>

#define Bc 32
#define Lc 4096
#define Cc 64
#define Dc 128
#define Kc 2048
#define NCHUNK 32   // 4096 / 128 rows per sparse chunk

// Scratch (no allocations allowed in kernel_launch)
__device__ float         g_scores[Bc * Lc];
__device__ unsigned char g_flags [Bc * Lc];
__device__ float         g_part  [Bc * NCHUNK * Dc];
__device__ float         g_agg   [Bc * Dc];

// ---------------------------------------------------------------------------
// 1. scores[b,l] = dot(x[b,l,:], score_w) + score_b   (one warp per row)
// ---------------------------------------------------------------------------
__global__ void scores_kernel(const float* __restrict__ x,
                              const float* __restrict__ sw,
                              const float* __restrict__ sb)
{
    int lane = threadIdx.x & 31;
    int warp = threadIdx.x >> 5;
    int row  = blockIdx.x * 8 + warp;          // grid = B*L/8
    const float* xr = x + (size_t)row * Cc;
    float s = xr[lane] * sw[lane] + xr[lane + 32] * sw[lane + 32];
    #pragma unroll
    for (int off = 16; off; off >>= 1) s += __shfl_xor_sync(0xffffffffu, s, off);
    if (lane == 0) g_scores[row] = s + sb[0];
}

// ---------------------------------------------------------------------------
// 2. Per-batch radix select of K-th largest score, set selection flags.
//    Tie handling matches lax.top_k (lower index wins among equal values).
// ---------------------------------------------------------------------------
__global__ void select_kernel()
{
    __shared__ unsigned keys[Lc];        // 16 KB
    __shared__ int      hist[8][16];     // per-warp histograms
    __shared__ unsigned s_prefix;
    __shared__ int      s_rem, s_cgt, s_ceq;

    int tid = threadIdx.x;               // 256 threads
    int wid = tid >> 5;
    int b   = blockIdx.x;

    for (int i = tid; i < Lc; i += 256) {
        unsigned u = __float_as_uint(g_scores[b * Lc + i]);
        // monotonic (ascending) transform of float ordering
        keys[i] = u ^ ((u >> 31) ? 0xFFFFFFFFu : 0x80000000u);
    }
    if (tid == 0) { s_prefix = 0u; s_rem = Kc; s_cgt = 0; s_ceq = 0; }
    __syncthreads();

    // 8 passes of 4 bits, MSB first: find threshold T = K-th largest key
    for (int shift = 28; shift >= 0; shift -= 4) {
        unsigned maskHigh = (shift == 28) ? 0u : (0xFFFFFFFFu << (shift + 4));
        if ((tid & 31) < 16) hist[wid][tid & 31] = 0;
        __syncthreads();
        unsigned prefix = s_prefix;
        for (int i = tid; i < Lc; i += 256) {
            unsigned k = keys[i];
            if ((k & maskHigh) == prefix)
                atomicAdd(&hist[wid][(k >> shift) & 15], 1);
        }
        __syncthreads();
        if (tid == 0) {
            int rem = s_rem;
            for (int d = 15; d >= 0; d--) {
                int c = 0;
                #pragma unroll
                for (int w = 0; w < 8; w++) c += hist[w][d];
                if (rem > c) rem -= c;
                else { s_prefix = prefix | ((unsigned)d << shift); break; }
            }
            s_rem = rem;
        }
        __syncthreads();
    }
    unsigned T = s_prefix;

    // counts of (> T) and (== T)
    int gt = 0, eq = 0;
    for (int i = tid; i < Lc; i += 256) {
        gt += (keys[i] > T);
        eq += (keys[i] == T);
    }
    #pragma unroll
    for (int off = 16; off; off >>= 1) {
        gt += __shfl_xor_sync(0xffffffffu, gt, off);
        eq += __shfl_xor_sync(0xffffffffu, eq, off);
    }
    if ((tid & 31) == 0) { atomicAdd(&s_cgt, gt); atomicAdd(&s_ceq, eq); }
    __syncthreads();

    int  cgt       = s_cgt;
    int  budget    = Kc - cgt;
    bool markAllEq = (s_ceq == budget);   // ~always (distinct floats)

    for (int i = tid; i < Lc; i += 256) {
        unsigned k = keys[i];
        g_flags[b * Lc + i] = (k > T) || (markAllEq && (k == T));
    }
    __syncthreads();
    if (!markAllEq && tid == 0) {         // rare tie path: lower index first
        int m = budget;
        for (int i = 0; i < Lc; i++) {
            if (keys[i] == T) { g_flags[b * Lc + i] = (m > 0) ? 1 : 0; m--; }
        }
    }
}

// ---------------------------------------------------------------------------
// 3. Sparse path: partial sums of gelu(x_sel @ sparse_w + sparse_b) per chunk.
//    Weights held in registers (64 floats / thread); x rows broadcast via smem.
// ---------------------------------------------------------------------------
__global__ void __launch_bounds__(128)
sparse_kernel(const float* __restrict__ x,
              const float* __restrict__ spw,
              const float* __restrict__ spb)
{
    int d     = threadIdx.x;             // output feature 0..127
    int blk   = blockIdx.x;              // B*NCHUNK blocks
    int b     = blk >> 5, chunk = blk & 31;
    int rowBase = b * Lc + chunk * 128;

    float wreg[Cc];
    #pragma unroll
    for (int c = 0; c < Cc; c++) wreg[c] = spw[c * Dc + d];
    float bias = spb[d];

    __shared__ float xs[2][Cc];
    float acc = 0.f;

    for (int r = 0; r < 128; r += 2) {
        __syncthreads();
        { int rr = d >> 6, cc = d & 63;
          xs[rr][cc] = x[(size_t)(rowBase + r + rr) * Cc + cc]; }
        __syncthreads();
        int f0 = g_flags[rowBase + r];
        int f1 = g_flags[rowBase + r + 1];
        if (f0 | f1) {                    // block-uniform branch
            float p0 = bias, p1 = bias;
            #pragma unroll
            for (int c = 0; c < Cc; c += 4) {
                float4 a0 = *(const float4*)&xs[0][c];
                float4 a1 = *(const float4*)&xs[1][c];
                p0 += a0.x*wreg[c] + a0.y*wreg[c+1] + a0.z*wreg[c+2] + a0.w*wreg[c+3];
                p1 += a1.x*wreg[c] + a1.y*wreg[c+1] + a1.z*wreg[c+2] + a1.w*wreg[c+3];
            }
            if (f0) acc += 0.5f * p0 * (1.f + erff(p0 * 0.70710678118654752440f));
            if (f1) acc += 0.5f * p1 * (1.f + erff(p1 * 0.70710678118654752440f));
        }
    }
    g_part[blk * Dc + d] = acc;
}

// ---------------------------------------------------------------------------
// 4. Deterministic reduce of partials -> mean over K
// ---------------------------------------------------------------------------
__global__ void agg_kernel()
{
    int d = threadIdx.x, b = blockIdx.x;
    float s = 0.f;
    #pragma unroll
    for (int j = 0; j < NCHUNK; j++) s += g_part[(b * NCHUNK + j) * Dc + d];
    g_agg[b * Dc + d] = s * (1.0f / (float)Kc);
}

// ---------------------------------------------------------------------------
// 5. full_feat = x @ full_w + full_b + agg, then LayerNorm over D=128.
//    Register-resident weights; 2 rows per iteration; shfl + smem LN reduce.
// ---------------------------------------------------------------------------
__global__ void __launch_bounds__(128)
full_kernel(const float* __restrict__ x,  const float* __restrict__ fw,
            const float* __restrict__ fb, const float* __restrict__ lg,
            const float* __restrict__ lb, float* __restrict__ out)
{
    const int ROWS = 128;
    int d       = threadIdx.x;
    int rowBase = blockIdx.x * ROWS;      // grid = B*L/128 = 1024
    int b       = rowBase >> 12;          // / L

    float wreg[Cc];
    #pragma unroll
    for (int c = 0; c < Cc; c++) wreg[c] = fw[c * Dc + d];
    float base = fb[d] + g_agg[b * Dc + d];
    float gam  = lg[d], bet = lb[d];

    __shared__ float xs[2][Cc];
    __shared__ float red[2][4][2];        // [row][warp][sum|sumsq]
    int lane = d & 31, w = d >> 5;

    for (int r = 0; r < ROWS; r += 2) {
        __syncthreads();                  // protect xs/red reuse
        { int rr = d >> 6, cc = d & 63;
          xs[rr][cc] = x[(size_t)(rowBase + r + rr) * Cc + cc]; }
        __syncthreads();

        float p0 = base, p1 = base;
        #pragma unroll
        for (int c = 0; c < Cc; c += 4) {
            float4 a0 = *(const float4*)&xs[0][c];
            float4 a1 = *(const float4*)&xs[1][c];
            p0 += a0.x*wreg[c] + a0.y*wreg[c+1] + a0.z*wreg[c+2] + a0.w*wreg[c+3];
            p1 += a1.x*wreg[c] + a1.y*wreg[c+1] + a1.z*wreg[c+2] + a1.w*wreg[c+3];
        }

        // LayerNorm reductions (4 independent chains interleaved)
        float s0 = p0, q0 = p0 * p0, s1 = p1, q1 = p1 * p1;
        #pragma unroll
        for (int off = 16; off; off >>= 1) {
            s0 += __shfl_xor_sync(0xffffffffu, s0, off);
            q0 += __shfl_xor_sync(0xffffffffu, q0, off);
            s1 += __shfl_xor_sync(0xffffffffu, s1, off);
            q1 += __shfl_xor_sync(0xffffffffu, q1, off);
        }
        if (lane == 0) {
            red[0][w][0] = s0; red[0][w][1] = q0;
            red[1][w][0] = s1; red[1][w][1] = q1;
        }
        __syncthreads();
        float S0 = red[0][0][0] + red[0][1][0] + red[0][2][0] + red[0][3][0];
        float Q0 = red[0][0][1] + red[0][1][1] + red[0][2][1] + red[0][3][1];
        float S1 = red[1][0][0] + red[1][1][0] + red[1][2][0] + red[1][3][0];
        float Q1 = red[1][0][1] + red[1][1][1] + red[1][2][1] + red[1][3][1];

        const float invD = 1.0f / 128.0f;
        float mu0 = S0 * invD, var0 = Q0 * invD - mu0 * mu0;
        float mu1 = S1 * invD, var1 = Q1 * invD - mu1 * mu1;
        float i0 = rsqrtf(var0 + 1e-5f), i1 = rsqrtf(var1 + 1e-5f);

        out[(size_t)(rowBase + r)     * Dc + d] = (p0 - mu0) * i0 * gam + bet;
        out[(size_t)(rowBase + r + 1) * Dc + d] = (p1 - mu1) * i1 * gam + bet;
    }
}

// ---------------------------------------------------------------------------
extern "C" void kernel_launch(void* const* d_in, const int* in_sizes, int n_in,
                              void* d_out, int out_size)
{
    const float* x   = (const float*)d_in[0];
    const float* sw  = (const float*)d_in[1];
    const float* sb  = (const float*)d_in[2];
    const float* spw = (const float*)d_in[3];
    const float* spb = (const float*)d_in[4];
    const float* fw  = (const float*)d_in[5];
    const float* fb  = (const float*)d_in[6];
    const float* lg  = (const float*)d_in[7];
    const float* lb  = (const float*)d_in[8];
    float* out = (float*)d_out;

    scores_kernel<<<(Bc * Lc) / 8, 256>>>(x, sw, sb);
    select_kernel<<<Bc, 256>>>();
    sparse_kernel<<<Bc * NCHUNK, 128>>>(x, spw, spb);
    agg_kernel<<<Bc, Dc>>>();
    full_kernel<<<(Bc * Lc) / 128, 128>>>(x, fw, fb, lg, lb, out);
}

// round 2
// speedup vs baseline: 1.4815x; 1.4815x over previous
#include <cuda_runtime.h>
#include <math.h>

#define Bc 32
#define Lc 4096
#define Cc 64
#define Dc 128
#define Kc 2048
#define NCHUNK 32   // 4096 / 128 rows per sparse chunk

// Scratch (no allocations allowed in kernel_launch)
__device__ float         g_scores[Bc * Lc];
__device__ unsigned char g_flags [Bc * Lc];
__device__ float         g_part  [Bc * NCHUNK * Dc];

// packed f32x2 helpers -------------------------------------------------------
__device__ __forceinline__ unsigned long long pack2(float lo, float hi) {
    unsigned long long u;
    asm("mov.b64 %0, {%1, %2};" : "=l"(u) : "f"(lo), "f"(hi));
    return u;
}
__device__ __forceinline__ void unpack2(unsigned long long u, float& lo, float& hi) {
    asm("mov.b64 {%0, %1}, %2;" : "=f"(lo), "=f"(hi) : "l"(u));
}
#define FMA2(acc, a, b) \
    asm("fma.rn.f32x2 %0, %1, %2, %0;" : "+l"(acc) : "l"(a), "l"(b))

// ---------------------------------------------------------------------------
// 1. scores[b,l] = dot(x[b,l,:], score_w) + score_b   (one warp per row)
// ---------------------------------------------------------------------------
__global__ void scores_kernel(const float* __restrict__ x,
                              const float* __restrict__ sw,
                              const float* __restrict__ sb)
{
    int lane = threadIdx.x & 31;
    int warp = threadIdx.x >> 5;
    int row  = blockIdx.x * 8 + warp;          // grid = B*L/8
    const float* xr = x + (size_t)row * Cc;
    float s = xr[lane] * sw[lane] + xr[lane + 32] * sw[lane + 32];
    #pragma unroll
    for (int off = 16; off; off >>= 1) s += __shfl_xor_sync(0xffffffffu, s, off);
    if (lane == 0) g_scores[row] = s + sb[0];
}

// ---------------------------------------------------------------------------
// 2. Per-batch radix select of K-th largest score, set selection flags.
//    match_any-aggregated smem atomics (scores cluster in few exponent bins).
// ---------------------------------------------------------------------------
__global__ void select_kernel()
{
    __shared__ unsigned keys[Lc];        // 16 KB
    __shared__ int      hist[8][16];     // per-warp histograms
    __shared__ unsigned s_prefix;
    __shared__ int      s_rem, s_cgt, s_ceq;

    int tid = threadIdx.x;               // 256 threads
    int wid = tid >> 5;
    int b   = blockIdx.x;

    for (int i = tid; i < Lc; i += 256) {
        unsigned u = __float_as_uint(g_scores[b * Lc + i]);
        keys[i] = u ^ (((unsigned)((int)u >> 31)) | 0x80000000u);
    }
    if (tid == 0) { s_prefix = 0u; s_rem = Kc; s_cgt = 0; s_ceq = 0; }
    __syncthreads();

    for (int shift = 28; shift >= 0; shift -= 4) {
        unsigned maskHigh = (shift == 28) ? 0u : (0xFFFFFFFFu << (shift + 4));
        if ((tid & 31) < 16) hist[wid][tid & 31] = 0;
        __syncthreads();
        unsigned prefix = s_prefix;
        for (int i = tid; i < Lc; i += 256) {
            unsigned k = keys[i];
            if ((k & maskHigh) == prefix) {
                int bin = (k >> shift) & 15;
                unsigned mmask = __activemask();
                unsigned grp   = __match_any_sync(mmask, bin);
                if ((tid & 31) == (__ffs(grp) - 1))
                    atomicAdd(&hist[wid][bin], __popc(grp));
            }
        }
        __syncthreads();
        if (tid == 0) {
            int rem = s_rem;
            for (int d = 15; d >= 0; d--) {
                int c = 0;
                #pragma unroll
                for (int w = 0; w < 8; w++) c += hist[w][d];
                if (rem > c) rem -= c;
                else { s_prefix = prefix | ((unsigned)d << shift); break; }
            }
            s_rem = rem;
        }
        __syncthreads();
    }
    unsigned T = s_prefix;

    int gt = 0, eq = 0;
    for (int i = tid; i < Lc; i += 256) {
        gt += (keys[i] > T);
        eq += (keys[i] == T);
    }
    #pragma unroll
    for (int off = 16; off; off >>= 1) {
        gt += __shfl_xor_sync(0xffffffffu, gt, off);
        eq += __shfl_xor_sync(0xffffffffu, eq, off);
    }
    if ((tid & 31) == 0) { atomicAdd(&s_cgt, gt); atomicAdd(&s_ceq, eq); }
    __syncthreads();

    int  budget    = Kc - s_cgt;
    bool markAllEq = (s_ceq == budget);   // ~always (distinct floats)

    for (int i = tid; i < Lc; i += 256) {
        unsigned k = keys[i];
        g_flags[b * Lc + i] = (k > T) || (markAllEq && (k == T));
    }
    __syncthreads();
    if (!markAllEq && tid == 0) {         // rare tie path: lower index first
        int m = budget;
        for (int i = 0; i < Lc; i++) {
            if (keys[i] == T) { g_flags[b * Lc + i] = (m > 0) ? 1 : 0; m--; }
        }
    }
}

// ---------------------------------------------------------------------------
// 3. Sparse path: partial sums of gelu(x_sel @ sparse_w + sparse_b) per chunk.
//    Packed-weight FFMA2, 8 rows per smem round, per-row uniform flag skip.
// ---------------------------------------------------------------------------
__global__ void __launch_bounds__(128, 4)
sparse_kernel(const float* __restrict__ x,
              const float* __restrict__ spw,
              const float* __restrict__ spb)
{
    int d       = threadIdx.x;            // output feature 0..127
    int blk     = blockIdx.x;             // B*NCHUNK blocks
    int rowBase = blk * 128;               // == b*Lc + chunk*128

    unsigned long long wp[32];
    #pragma unroll
    for (int i = 0; i < 32; i++)
        wp[i] = pack2(spw[(2 * i) * Dc + d], spw[(2 * i + 1) * Dc + d]);
    float bias = spb[d];

    __shared__ __align__(16) float xs[8][Cc];
    float acc = 0.f;

    for (int r0 = 0; r0 < 128; r0 += 8) {
        __syncthreads();
        ((float4*)&xs[0][0])[d] =
            ((const float4*)(x + (size_t)(rowBase + r0) * Cc))[d];
        unsigned long long flags8 =
            *(const unsigned long long*)&g_flags[rowBase + r0];
        __syncthreads();
        #pragma unroll
        for (int r = 0; r < 8; r++) {
            if ((flags8 >> (8 * r)) & 1) {      // block-uniform branch
                unsigned long long a = 0;
                const ulonglong2* xr = (const ulonglong2*)&xs[r][0];
                #pragma unroll
                for (int i = 0; i < 16; i++) {
                    ulonglong2 v = xr[i];
                    FMA2(a, v.x, wp[2 * i]);
                    FMA2(a, v.y, wp[2 * i + 1]);
                }
                float lo, hi; unpack2(a, lo, hi);
                float p = bias + lo + hi;
                acc += 0.5f * p * (1.f + erff(p * 0.70710678118654752440f));
            }
        }
    }
    g_part[blk * Dc + d] = acc;
}

// ---------------------------------------------------------------------------
// 4. full_feat = x @ full_w + full_b + agg, then LayerNorm over D=128.
//    Packed-weight FFMA2, 8-row LN rounds; agg reduced in prologue.
// ---------------------------------------------------------------------------
__global__ void __launch_bounds__(128, 4)
full_kernel(const float* __restrict__ x,  const float* __restrict__ fw,
            const float* __restrict__ fb, const float* __restrict__ lg,
            const float* __restrict__ lb, float* __restrict__ out)
{
    int d       = threadIdx.x;
    int rowBase = blockIdx.x * 128;       // grid = B*L/128 = 1024
    int b       = rowBase >> 12;          // / L

    unsigned long long wp[32];
    #pragma unroll
    for (int i = 0; i < 32; i++)
        wp[i] = pack2(fw[(2 * i) * Dc + d], fw[(2 * i + 1) * Dc + d]);

    float aggv = 0.f;                     // deterministic partial reduce
    #pragma unroll
    for (int j = 0; j < NCHUNK; j++) aggv += g_part[(b * NCHUNK + j) * Dc + d];
    float base = fb[d] + aggv * (1.0f / (float)Kc);
    float gam  = lg[d], bet = lb[d];

    __shared__ __align__(16) float xs[8][Cc];
    __shared__ float red[8][4][2];        // [row][warp][sum|sumsq]
    int lane = d & 31, w = d >> 5;

    for (int r0 = 0; r0 < 128; r0 += 8) {
        __syncthreads();                                   // protect xs
        ((float4*)&xs[0][0])[d] =
            ((const float4*)(x + (size_t)(rowBase + r0) * Cc))[d];
        __syncthreads();

        float p[8];
        #pragma unroll
        for (int r = 0; r < 8; r++) {
            unsigned long long a = 0;
            const ulonglong2* xr = (const ulonglong2*)&xs[r][0];
            #pragma unroll
            for (int i = 0; i < 16; i++) {
                ulonglong2 v = xr[i];
                FMA2(a, v.x, wp[2 * i]);
                FMA2(a, v.y, wp[2 * i + 1]);
            }
            float lo, hi; unpack2(a, lo, hi);
            p[r] = base + lo + hi;
        }

        // LayerNorm reductions: warp shfl then cross-warp via smem
        #pragma unroll
        for (int r = 0; r < 8; r++) {
            float s = p[r], q = p[r] * p[r];
            #pragma unroll
            for (int off = 16; off; off >>= 1) {
                s += __shfl_xor_sync(0xffffffffu, s, off);
                q += __shfl_xor_sync(0xffffffffu, q, off);
            }
            if (lane == 0) { red[r][w][0] = s; red[r][w][1] = q; }
        }
        __syncthreads();

        const float invD = 1.0f / 128.0f;
        #pragma unroll
        for (int r = 0; r < 8; r++) {
            float S = red[r][0][0] + red[r][1][0] + red[r][2][0] + red[r][3][0];
            float Q = red[r][0][1] + red[r][1][1] + red[r][2][1] + red[r][3][1];
            float mu  = S * invD;
            float var = Q * invD - mu * mu;
            float inv = rsqrtf(var + 1e-5f);
            out[(size_t)(rowBase + r0 + r) * Dc + d] = (p[r] - mu) * inv * gam + bet;
        }
    }
}

// ---------------------------------------------------------------------------
extern "C" void kernel_launch(void* const* d_in, const int* in_sizes, int n_in,
                              void* d_out, int out_size)
{
    const float* x   = (const float*)d_in[0];
    const float* sw  = (const float*)d_in[1];
    const float* sb  = (const float*)d_in[2];
    const float* spw = (const float*)d_in[3];
    const float* spb = (const float*)d_in[4];
    const float* fw  = (const float*)d_in[5];
    const float* fb  = (const float*)d_in[6];
    const float* lg  = (const float*)d_in[7];
    const float* lb  = (const float*)d_in[8];
    float* out = (float*)d_out;

    scores_kernel<<<(Bc * Lc) / 8, 256>>>(x, sw, sb);
    select_kernel<<<Bc, 256>>>();
    sparse_kernel<<<Bc * NCHUNK, 128>>>(x, spw, spb);
    full_kernel<<<(Bc * Lc) / 128, 128>>>(x, fw, fb, lg, lb, out);
}